// round 8
// baseline (speedup 1.0000x reference)
#include <cuda_runtime.h>
#include <cuda_bf16.h>
#include <math.h>

#define BB 32
#define TT 64
#define BT 2048
#define HID 200
#define FEAT 6144
#define SPLITS 8

typedef unsigned long long ull;

// -------------------- f32x2 packed helpers (sm_103a FFMA2) -------------------
__device__ __forceinline__ ull pk2(float lo, float hi) {
    ull r;
    asm("mov.b64 %0, {%1, %2};" : "=l"(r) : "f"(lo), "f"(hi));
    return r;
}
__device__ __forceinline__ ull fma2(ull a, ull b, ull c) {
    ull d;
    asm("fma.rn.f32x2 %0, %1, %2, %3;" : "=l"(d) : "l"(a), "l"(b), "l"(c));
    return d;
}
__device__ __forceinline__ float2 upk2(ull v) {
    float lo, hi;
    asm("mov.b64 {%0, %1}, %2;" : "=f"(lo), "=f"(hi) : "l"(v));
    return make_float2(lo, hi);
}

// -------------------- scratch (device globals; no allocs) --------------------
__device__ float g_xt  [BT * 3  * 1024];
__device__ float g_e1  [BT * 8  * 1024];
__device__ float g_e2  [BT * 16 * 256];
__device__ float g_e3  [BT * 32 * 64];
__device__ float g_d2  [BT * 16 * 256];
__device__ float g_d1  [BT * 8  * 1024];
__device__ float g_feat[BT * FEAT];
__device__ float g_h1  [BT * HID];
__device__ float g_h2  [BT * HID];
__device__ float g_part[SPLITS * BT * HID];

// -------------------- permute [B,C,H,W,T] -> [B*T,C,H,W] --------------------
__global__ void permute_kernel(const float* __restrict__ x, float* __restrict__ xt) {
    int bidx = blockIdx.x;
    int h = bidx & 31;
    int c = (bidx >> 5) % 3;
    int b = bidx / 96;
    __shared__ float s[32][65];
    const float* src = x + (size_t)(((b * 3 + c) * 32 + h) * 32) * 64;
    for (int i = threadIdx.x; i < 2048; i += blockDim.x) {
        int w = i >> 6, t = i & 63;
        s[w][t] = src[i];
    }
    __syncthreads();
    for (int i = threadIdx.x; i < 2048; i += blockDim.x) {
        int t = i >> 5, w = i & 31;
        xt[((size_t)((b * 64 + t) * 3 + c) << 10) + (h << 5) + w] = s[w][t];
    }
}

// -------------------- standard conv3x3 via FFMA2 (+opt maxpool, +ReLU) -------
// Input rows padded to HS+1 (R3-proven conflict-free). Weights duplicated as
// (w,w) pairs in SMEM with cog-padded layout -> one LDS.64 per weight pair.
template<int CA, int COUT, int COUT_T, int HS, int NBT, int NPIX, bool POOL>
__global__ void __launch_bounds__(256, 2)
conv_std_k(const float* __restrict__ inA, const float* __restrict__ wgt,
           const float* __restrict__ bias, float* __restrict__ out)
{
    constexpr int GP    = COUT / COUT_T;
    constexpr int PXT   = HS * HS / NPIX;
    constexpr int HP    = HS + 1;
    constexpr int CSZ   = HS * HP;
    constexpr int ASZP  = CA * CSZ;
    constexpr int BLKW  = 2 * COUT_T + 2;               // floats per (ci,kk,cog) block
    constexpr int W2SZ  = CA * 9 * GP * BLKW;           // duplicated weights (floats)
    constexpr int KWS   = GP * (COUT_T + 1);            // kw stride in ull units
    constexpr int NP2   = NPIX / 2;

    extern __shared__ float sm[];
    float* sW2 = sm;                  // duplicated pairs
    float* sBi = sW2 + W2SZ;
    float* sIn = sBi + COUT;

    const int tid = threadIdx.x, NT = blockDim.x;
    const int bt0 = blockIdx.x * NBT;

    // fill duplicated weights: block ((ci*9+kk)*GP+cog), entry 2*co{,+1}
    for (int i = tid; i < CA * 9 * GP * COUT_T; i += NT) {
        int co  = i % COUT_T;
        int cog = (i / COUT_T) % GP;
        int kk  = (i / (COUT_T * GP)) % 9;
        int ci  = i / (COUT_T * GP * 9);
        float v = wgt[((cog * COUT_T + co) * CA + ci) * 9 + kk];
        int base = ((ci * 9 + kk) * GP + cog) * BLKW + 2 * co;
        sW2[base] = v;
        sW2[base + 1] = v;
    }
    for (int i = tid; i < COUT; i += NT) sBi[i] = bias[i];

    for (int i = tid; i < NBT * CA * HS * HS; i += NT) {
        int nn = i / (CA * HS * HS), rr = i % (CA * HS * HS);
        int c = rr / (HS * HS), pp = rr % (HS * HS);
        int hh = pp / HS, ww = pp % HS;
        float v;
        if (POOL) {
            const float* s = inA + (size_t)((bt0 + nn) * CA + c) * (4 * HS * HS)
                                 + (2 * hh) * (2 * HS) + 2 * ww;
            v = fmaxf(fmaxf(s[0], s[1]), fmaxf(s[2 * HS], s[2 * HS + 1]));
        } else {
            v = inA[(size_t)(bt0 + nn) * (CA * HS * HS) + rr];
        }
        sIn[nn * ASZP + c * CSZ + hh * HP + ww] = v;
    }
    __syncthreads();

    const int n   = tid / (GP * PXT);
    const int r   = tid % (GP * PXT);
    const int cog = r / PXT;
    const int p   = r % PXT;
    const int h   = p / (HS / NPIX);
    const int w0  = (p % (HS / NPIX)) * NPIX;
    const float* sI = sIn + n * ASZP;

    ull accP[COUT_T][NP2];
    #pragma unroll
    for (int co = 0; co < COUT_T; co++) {
        ull b2 = pk2(sBi[cog * COUT_T + co], sBi[cog * COUT_T + co]);
        #pragma unroll
        for (int j = 0; j < NP2; j++) accP[co][j] = b2;
    }

    #pragma unroll 1
    for (int ci = 0; ci < CA; ci++) {
        const float* ch = sI + ci * CSZ;
        #pragma unroll
        for (int kh = 0; kh < 3; kh++) {
            int ih = h + kh - 1;
            bool rowok = (ih >= 0) && (ih < HS);
            float v[NPIX + 2];
            #pragma unroll
            for (int j = 0; j < NPIX + 2; j++) {
                int iw = w0 + j - 1;
                v[j] = (rowok && iw >= 0 && iw < HS) ? ch[ih * HP + iw] : 0.f;
            }
            ull pkE[NP2 + 1], pkO[NP2];
            #pragma unroll
            for (int q = 0; q <= NP2; q++) pkE[q] = pk2(v[2 * q], v[2 * q + 1]);
            #pragma unroll
            for (int q = 0; q < NP2; q++) pkO[q] = pk2(v[2 * q + 1], v[2 * q + 2]);

            const ull* wr2 = reinterpret_cast<const ull*>(sW2) +
                             (size_t)((ci * 9 + kh * 3) * GP + cog) * (COUT_T + 1);
            #pragma unroll
            for (int co = 0; co < COUT_T; co++) {
                ull wa2 = wr2[co];
                ull wb2 = wr2[KWS + co];
                ull wc2 = wr2[2 * KWS + co];
                #pragma unroll
                for (int q = 0; q < NP2; q++)
                    accP[co][q] = fma2(wa2, pkE[q],
                                  fma2(wb2, pkO[q],
                                  fma2(wc2, pkE[q + 1], accP[co][q])));
            }
        }
    }

    const int btn = bt0 + n;
    #pragma unroll
    for (int co = 0; co < COUT_T; co++) {
        float* op = out + (size_t)((btn * COUT + cog * COUT_T + co) * HS + h) * HS + w0;
        #pragma unroll
        for (int q = 0; q < NP2; q += 2) {
            float2 a = upk2(accP[co][q]);
            float2 b = upk2(accP[co][q + 1]);
            *reinterpret_cast<float4*>(op + 2 * q) =
                make_float4(fmaxf(a.x, 0.f), fmaxf(a.y, 0.f),
                            fmaxf(b.x, 0.f), fmaxf(b.y, 0.f));
        }
    }
}

// -------------------- decoder conv3x3 over [up2x(A), B] via FFMA2 + ReLU -----
// A at coarse HA=HS/2, parity-folded 2x2 stencil (packed heterogeneous weight
// pairs); B fine 3x3 with duplicated-pair weights. R3 padded-pitch tiles.
template<int CA, int CB, int COUT, int COUT_T, int HS, int NBT, int NPIX>
__global__ void __launch_bounds__(256, 2)
conv_up_k(const float* __restrict__ inA, const float* __restrict__ inB,
          const float* __restrict__ wgt, const float* __restrict__ bias,
          float* __restrict__ out)
{
    constexpr int CIN   = CA + CB;
    constexpr int HA    = HS / 2;
    constexpr int HAP   = HA + 1;
    constexpr int HP    = HS + 1;
    constexpr int CASZ  = HA * HAP;
    constexpr int CBSZ  = HS * HP;
    constexpr int ASZP  = CA * CASZ;
    constexpr int TSZ   = ASZP + CB * CBSZ;
    constexpr int GP    = COUT / COUT_T;
    constexpr int PXT   = HS * HS / NPIX;
    constexpr int WASZ  = CA * 9 * COUT;                // scalar A weights
    constexpr int BLKW  = 2 * COUT_T + 2;
    constexpr int WB2SZ = CB * 9 * GP * BLKW;           // duplicated B weights
    constexpr int KWS   = GP * (COUT_T + 1);
    constexpr int NP2   = NPIX / 2;
    constexpr int NC    = NP2 + 2;

    extern __shared__ float sm[];
    float* sWA  = sm;                 // transposed scalar [CA*9][COUT]
    float* sBi  = sWA + WASZ;
    float* sWB2 = sBi + COUT;
    float* sIn  = sWB2 + WB2SZ;

    const int tid = threadIdx.x, NT = blockDim.x;
    const int bt0 = blockIdx.x * NBT;

    for (int i = tid; i < WASZ; i += NT) {
        int co = i % COUT;
        int rest = i / COUT;
        int ci = rest / 9, kk = rest % 9;
        sWA[i] = wgt[(co * CIN + ci) * 9 + kk];
    }
    for (int i = tid; i < COUT; i += NT) sBi[i] = bias[i];
    for (int i = tid; i < CB * 9 * GP * COUT_T; i += NT) {
        int co  = i % COUT_T;
        int cog = (i / COUT_T) % GP;
        int kk  = (i / (COUT_T * GP)) % 9;
        int ci  = i / (COUT_T * GP * 9);
        float v = wgt[((cog * COUT_T + co) * CIN + CA + ci) * 9 + kk];
        int base = ((ci * 9 + kk) * GP + cog) * BLKW + 2 * co;
        sWB2[base] = v;
        sWB2[base + 1] = v;
    }
    for (int i = tid; i < NBT * CA * HA * HA; i += NT) {
        int nn = i / (CA * HA * HA), rr = i % (CA * HA * HA);
        int c = rr / (HA * HA), pp = rr % (HA * HA);
        sIn[nn * TSZ + c * CASZ + (pp / HA) * HAP + (pp % HA)] =
            inA[(size_t)(bt0 + nn) * (CA * HA * HA) + rr];
    }
    for (int i = tid; i < NBT * CB * HS * HS; i += NT) {
        int nn = i / (CB * HS * HS), rr = i % (CB * HS * HS);
        int c = rr / (HS * HS), pp = rr % (HS * HS);
        sIn[nn * TSZ + ASZP + c * CBSZ + (pp / HS) * HP + (pp % HS)] =
            inB[(size_t)(bt0 + nn) * (CB * HS * HS) + rr];
    }
    __syncthreads();

    const int n   = tid / (GP * PXT);
    const int r   = tid % (GP * PXT);
    const int cog = r / PXT;
    const int p   = r % PXT;
    const int h   = p / (HS / NPIX);
    const int w0  = (p % (HS / NPIX)) * NPIX;
    const float* sI = sIn + n * TSZ;

    ull accP[COUT_T][NP2];
    #pragma unroll
    for (int co = 0; co < COUT_T; co++) {
        ull b2 = pk2(sBi[cog * COUT_T + co], sBi[cog * COUT_T + co]);
        #pragma unroll
        for (int j = 0; j < NP2; j++) accP[co][j] = b2;
    }

    // ---- A part: coarse 2x2 stencil, packed heterogeneous weight pairs ----
    const int  a    = h >> 1;
    const bool hodd = (h & 1) != 0;
    const int  rowA = hodd ? a : a - 1;
    const int  rowB = hodd ? a + 1 : a;
    const int  cs0  = (w0 >> 1) - 1;

    #pragma unroll 1
    for (int ci = 0; ci < CA; ci++) {
        const float* ch = sI + ci * CASZ;
        float cAr[NC], cBr[NC];
        #pragma unroll
        for (int k = 0; k < NC; k++) {
            int cc = cs0 + k;
            bool cok = (cc >= 0) && (cc < HA);
            cAr[k] = (cok && rowA >= 0) ? ch[rowA * HAP + cc] : 0.f;
            cBr[k] = (cok && rowB < HA) ? ch[rowB * HAP + cc] : 0.f;
        }
        ull pkA[NP2 + 1], pkB[NP2 + 1];
        #pragma unroll
        for (int q = 0; q <= NP2; q++) {
            pkA[q] = pk2(cAr[q], cAr[q + 1]);
            pkB[q] = pk2(cBr[q], cBr[q + 1]);
        }
        const float* wr = sWA + ci * 9 * COUT + cog * COUT_T;
        #pragma unroll
        for (int co = 0; co < COUT_T; co++) {
            float w00 = wr[0 * COUT + co], w01 = wr[1 * COUT + co], w02 = wr[2 * COUT + co];
            float w10 = wr[3 * COUT + co], w11 = wr[4 * COUT + co], w12 = wr[5 * COUT + co];
            float w20 = wr[6 * COUT + co], w21 = wr[7 * COUT + co], w22 = wr[8 * COUT + co];
            float rA0 = hodd ? (w00 + w10) : w00;
            float rA1 = hodd ? (w01 + w11) : w01;
            float rA2 = hodd ? (w02 + w12) : w02;
            float rB0 = hodd ? w20 : (w10 + w20);
            float rB1 = hodd ? w21 : (w11 + w21);
            float rB2 = hodd ? w22 : (w12 + w22);
            // packed pairs: lo half = even-j weight, hi half = odd-j weight
            ull wA1 = pk2(rA0, rA0 + rA1);
            ull wA2 = pk2(rA1 + rA2, rA2);
            ull wB1 = pk2(rB0, rB0 + rB1);
            ull wB2 = pk2(rB1 + rB2, rB2);
            #pragma unroll
            for (int q = 0; q < NP2; q++) {
                accP[co][q] = fma2(wA1, pkA[q],     accP[co][q]);
                accP[co][q] = fma2(wA2, pkA[q + 1], accP[co][q]);
                accP[co][q] = fma2(wB1, pkB[q],     accP[co][q]);
                accP[co][q] = fma2(wB2, pkB[q + 1], accP[co][q]);
            }
        }
    }

    // ---- B part: fine 3x3 via FFMA2 ----
    #pragma unroll 1
    for (int ci = 0; ci < CB; ci++) {
        const float* ch = sI + ASZP + ci * CBSZ;
        #pragma unroll
        for (int kh = 0; kh < 3; kh++) {
            int ih = h + kh - 1;
            bool rowok = (ih >= 0) && (ih < HS);
            float v[NPIX + 2];
            #pragma unroll
            for (int j = 0; j < NPIX + 2; j++) {
                int iw = w0 + j - 1;
                v[j] = (rowok && iw >= 0 && iw < HS) ? ch[ih * HP + iw] : 0.f;
            }
            ull pkE[NP2 + 1], pkO[NP2];
            #pragma unroll
            for (int q = 0; q <= NP2; q++) pkE[q] = pk2(v[2 * q], v[2 * q + 1]);
            #pragma unroll
            for (int q = 0; q < NP2; q++) pkO[q] = pk2(v[2 * q + 1], v[2 * q + 2]);

            const ull* wr2 = reinterpret_cast<const ull*>(sWB2) +
                             (size_t)((ci * 9 + kh * 3) * GP + cog) * (COUT_T + 1);
            #pragma unroll
            for (int co = 0; co < COUT_T; co++) {
                ull wa2 = wr2[co];
                ull wb2 = wr2[KWS + co];
                ull wc2 = wr2[2 * KWS + co];
                #pragma unroll
                for (int q = 0; q < NP2; q++)
                    accP[co][q] = fma2(wa2, pkE[q],
                                  fma2(wb2, pkO[q],
                                  fma2(wc2, pkE[q + 1], accP[co][q])));
            }
        }
    }

    const int btn = bt0 + n;
    #pragma unroll
    for (int co = 0; co < COUT_T; co++) {
        float* op = out + (size_t)((btn * COUT + cog * COUT_T + co) * HS + h) * HS + w0;
        #pragma unroll
        for (int q = 0; q < NP2; q += 2) {
            float2 a = upk2(accP[co][q]);
            float2 b = upk2(accP[co][q + 1]);
            *reinterpret_cast<float4*>(op + 2 * q) =
                make_float4(fmaxf(a.x, 0.f), fmaxf(a.y, 0.f),
                            fmaxf(b.x, 0.f), fmaxf(b.y, 0.f));
        }
    }
}

// -------------------- 1x1 conv -> softmax(3ch incl. ones) -> masked feat ----
__global__ void mask_feat_kernel(const float* __restrict__ d1, const float* __restrict__ xt,
                                 const float* __restrict__ ow, const float* __restrict__ ob,
                                 float* __restrict__ feat)
{
    int idx = blockIdx.x * blockDim.x + threadIdx.x;
    if (idx >= BT * 1024) return;
    int bt = idx >> 10, hw = idx & 1023;
    const float* dp = d1 + (size_t)bt * 8 * 1024 + hw;
    float l0 = ob[0], l1 = ob[1];
    #pragma unroll
    for (int c = 0; c < 8; c++) {
        float v = dp[(size_t)c << 10];
        l0 = fmaf(v, ow[c], l0);
        l1 = fmaf(v, ow[8 + c], l1);
    }
    float mx = fmaxf(fmaxf(l0, l1), 1.0f);
    float e0 = expf(l0 - mx), e1 = expf(l1 - mx), e2 = expf(1.0f - mx);
    float inv = 1.0f / (e0 + e1 + e2);
    float m0 = e0 * inv, m1 = e1 * inv;

    const float* xp = xt + (size_t)bt * 3 * 1024 + hw;
    float* fp = feat + (size_t)bt * FEAT + hw;
    #pragma unroll
    for (int c = 0; c < 3; c++) {
        float xv = xp[(size_t)c << 10];
        fp[(size_t)c << 10]       = m0 * xv;
        fp[(size_t)(3 + c) << 10] = m1 * xv;
    }
}

// -------------------- GEMM1: split-K, BM256/BN64/BK16, TM16/TN4 --------------
__global__ void __launch_bounds__(256)
sgemm1_k(const float* __restrict__ A, const float* __restrict__ Bm,
         float* __restrict__ Cpart)
{
    constexpr int M = BT, N = HID, K = FEAT;
    constexpr int BM = 256, BN = 64, BK = 16;
    constexpr int KS = K / SPLITS;
    __shared__ float sA[BK][BM + 4];
    __shared__ float sB[BK][BN + 4];

    const int tid = threadIdx.x;
    const int tx = tid % 16;
    const int ty = tid / 16;
    const int bm = blockIdx.y * BM;
    const int bn = blockIdx.x * BN;
    const int kbase = blockIdx.z * KS;

    const int c4 = tid % 4;
    const int r0 = tid / 4;

    float acc[16][4];
    #pragma unroll
    for (int i = 0; i < 16; i++)
        #pragma unroll
        for (int j = 0; j < 4; j++) acc[i][j] = 0.f;

    for (int k0 = kbase; k0 < kbase + KS; k0 += BK) {
        #pragma unroll
        for (int q = 0; q < 4; q++) {
            int rr = r0 + 64 * q;
            float4 av = *reinterpret_cast<const float4*>(&A[(size_t)(bm + rr) * K + k0 + c4 * 4]);
            sA[c4 * 4 + 0][rr] = av.x;
            sA[c4 * 4 + 1][rr] = av.y;
            sA[c4 * 4 + 2][rr] = av.z;
            sA[c4 * 4 + 3][rr] = av.w;
        }
        {
            int kk = tid / 16;
            int cc = (tid % 16) * 4;
            int gcol = bn + cc;
            float4 bv;
            if (gcol + 3 < N) {
                bv = *reinterpret_cast<const float4*>(&Bm[(size_t)(k0 + kk) * N + gcol]);
            } else {
                bv.x = (gcol + 0 < N) ? Bm[(size_t)(k0 + kk) * N + gcol + 0] : 0.f;
                bv.y = (gcol + 1 < N) ? Bm[(size_t)(k0 + kk) * N + gcol + 1] : 0.f;
                bv.z = (gcol + 2 < N) ? Bm[(size_t)(k0 + kk) * N + gcol + 2] : 0.f;
                bv.w = (gcol + 3 < N) ? Bm[(size_t)(k0 + kk) * N + gcol + 3] : 0.f;
            }
            *reinterpret_cast<float4*>(&sB[kk][cc]) = bv;
        }
        __syncthreads();

        #pragma unroll
        for (int kk = 0; kk < BK; kk++) {
            float4 b = *reinterpret_cast<const float4*>(&sB[kk][tx * 4]);
            #pragma unroll
            for (int q = 0; q < 4; q++) {
                float4 a = *reinterpret_cast<const float4*>(&sA[kk][ty * 16 + q * 4]);
                acc[q * 4 + 0][0] = fmaf(a.x, b.x, acc[q * 4 + 0][0]);
                acc[q * 4 + 0][1] = fmaf(a.x, b.y, acc[q * 4 + 0][1]);
                acc[q * 4 + 0][2] = fmaf(a.x, b.z, acc[q * 4 + 0][2]);
                acc[q * 4 + 0][3] = fmaf(a.x, b.w, acc[q * 4 + 0][3]);
                acc[q * 4 + 1][0] = fmaf(a.y, b.x, acc[q * 4 + 1][0]);
                acc[q * 4 + 1][1] = fmaf(a.y, b.y, acc[q * 4 + 1][1]);
                acc[q * 4 + 1][2] = fmaf(a.y, b.z, acc[q * 4 + 1][2]);
                acc[q * 4 + 1][3] = fmaf(a.y, b.w, acc[q * 4 + 1][3]);
                acc[q * 4 + 2][0] = fmaf(a.z, b.x, acc[q * 4 + 2][0]);
                acc[q * 4 + 2][1] = fmaf(a.z, b.y, acc[q * 4 + 2][1]);
                acc[q * 4 + 2][2] = fmaf(a.z, b.z, acc[q * 4 + 2][2]);
                acc[q * 4 + 2][3] = fmaf(a.z, b.w, acc[q * 4 + 2][3]);
                acc[q * 4 + 3][0] = fmaf(a.w, b.x, acc[q * 4 + 3][0]);
                acc[q * 4 + 3][1] = fmaf(a.w, b.y, acc[q * 4 + 3][1]);
                acc[q * 4 + 3][2] = fmaf(a.w, b.z, acc[q * 4 + 3][2]);
                acc[q * 4 + 3][3] = fmaf(a.w, b.w, acc[q * 4 + 3][3]);
            }
        }
        __syncthreads();
    }

    float* Cp = Cpart + (size_t)blockIdx.z * M * N;
    #pragma unroll
    for (int i = 0; i < 16; i++) {
        int m = bm + ty * 16 + i;
        #pragma unroll
        for (int j = 0; j < 4; j++) {
            int n = bn + tx * 4 + j;
            if (n < N) Cp[(size_t)m * N + n] = acc[i][j];
        }
    }
}

__global__ void reduce8_relu_kernel(const float* __restrict__ part,
                                    const float* __restrict__ bias,
                                    float* __restrict__ out)
{
    int idx = blockIdx.x * blockDim.x + threadIdx.x;
    if (idx >= BT * HID) return;
    int n = idx % HID;
    float v = bias[n];
    #pragma unroll
    for (int s = 0; s < SPLITS; s++) v += part[(size_t)s * BT * HID + idx];
    out[idx] = fmaxf(v, 0.f);
}

// -------------------- tiled SGEMM (GEMM2, bias+relu) --------------------------
template<int BM, int BN, int BK, int TM, int TN, bool RELU>
__global__ void sgemm_k(int M, int N, int K,
                        const float* __restrict__ A, const float* __restrict__ Bm,
                        const float* __restrict__ bias, float* __restrict__ C)
{
    __shared__ float sA[BK][BM + 1];
    __shared__ float sB[BK][BN];
    const int tid = threadIdx.x;
    const int tx = tid % (BN / TN);
    const int ty = tid / (BN / TN);
    const int bm = blockIdx.y * BM;
    const int bn = blockIdx.x * BN;

    float acc[TM][TN];
    #pragma unroll
    for (int i = 0; i < TM; i++)
        #pragma unroll
        for (int j = 0; j < TN; j++) acc[i][j] = 0.f;

    for (int k0 = 0; k0 < K; k0 += BK) {
        for (int i = tid; i < BM * BK; i += 256) {
            int m = i / BK, kk = i % BK;
            sA[kk][m] = (bm + m < M && k0 + kk < K) ? A[(size_t)(bm + m) * K + k0 + kk] : 0.f;
        }
        for (int i = tid; i < BK * BN; i += 256) {
            int kk = i / BN, n = i % BN;
            sB[kk][n] = (k0 + kk < K && bn + n < N) ? Bm[(size_t)(k0 + kk) * N + bn + n] : 0.f;
        }
        __syncthreads();
        #pragma unroll
        for (int kk = 0; kk < BK; kk++) {
            float a[TM], b[TN];
            #pragma unroll
            for (int i = 0; i < TM; i++) a[i] = sA[kk][ty * TM + i];
            #pragma unroll
            for (int j = 0; j < TN; j++) b[j] = sB[kk][tx * TN + j];
            #pragma unroll
            for (int i = 0; i < TM; i++)
                #pragma unroll
                for (int j = 0; j < TN; j++) acc[i][j] = fmaf(a[i], b[j], acc[i][j]);
        }
        __syncthreads();
    }

    #pragma unroll
    for (int i = 0; i < TM; i++) {
        int m = bm + ty * TM + i;
        if (m >= M) continue;
        #pragma unroll
        for (int j = 0; j < TN; j++) {
            int n = bn + tx * TN + j;
            if (n >= N) continue;
            float v = acc[i][j] + bias[n];
            if (RELU) v = fmaxf(v, 0.f);
            C[(size_t)m * N + n] = v;
        }
    }
}

// -------------------- final 200->4 + tanh scale ------------------------------
__global__ void loc3_kernel(const float* __restrict__ h2, const float* __restrict__ w3,
                            const float* __restrict__ b3, float* __restrict__ out)
{
    int idx = blockIdx.x * blockDim.x + threadIdx.x;
    if (idx >= BT * 4) return;
    int m = idx >> 2, j = idx & 3;
    float acc = b3[j];
    const float* hp = h2 + (size_t)m * HID;
    #pragma unroll 8
    for (int k = 0; k < HID; k++) acc = fmaf(hp[k], w3[k * 4 + j], acc);
    out[idx] = tanhf(acc) * 16.f + 16.f;
}

// -------------------- launch --------------------------------------------------
extern "C" void kernel_launch(void* const* d_in, const int* in_sizes, int n_in,
                              void* d_out, int out_size)
{
    const float* x   = (const float*)d_in[0];
    const float* ew1 = (const float*)d_in[1];
    const float* eb1 = (const float*)d_in[2];
    const float* ew2 = (const float*)d_in[3];
    const float* eb2 = (const float*)d_in[4];
    const float* ew3 = (const float*)d_in[5];
    const float* eb3 = (const float*)d_in[6];
    const float* dw2 = (const float*)d_in[7];
    const float* db2 = (const float*)d_in[8];
    const float* dw1 = (const float*)d_in[9];
    const float* db1 = (const float*)d_in[10];
    const float* ow  = (const float*)d_in[11];
    const float* ob  = (const float*)d_in[12];
    const float* lw1 = (const float*)d_in[13];
    const float* lb1 = (const float*)d_in[14];
    const float* lw2 = (const float*)d_in[15];
    const float* lb2 = (const float*)d_in[16];
    const float* lw3 = (const float*)d_in[17];
    const float* lb3 = (const float*)d_in[18];
    float* out = (float*)d_out;

    float *xt, *e1, *e2, *e3, *d2v, *d1v, *feat, *h1, *h2, *part;
    cudaGetSymbolAddress((void**)&xt,   g_xt);
    cudaGetSymbolAddress((void**)&e1,   g_e1);
    cudaGetSymbolAddress((void**)&e2,   g_e2);
    cudaGetSymbolAddress((void**)&e3,   g_e3);
    cudaGetSymbolAddress((void**)&d2v,  g_d2);
    cudaGetSymbolAddress((void**)&d1v,  g_d1);
    cudaGetSymbolAddress((void**)&feat, g_feat);
    cudaGetSymbolAddress((void**)&h1,   g_h1);
    cudaGetSymbolAddress((void**)&h2,   g_h2);
    cudaGetSymbolAddress((void**)&part, g_part);

    // smem bytes: dup-weight blocks = CA*9*GP*(2*COUT_T+2) floats
    constexpr int SM_E1 = (3 * 9 * 1 * 18  + 8  + 2 * 3 * 32 * 33) * 4;                  // 27296
    constexpr int SM_E2 = (8 * 9 * 2 * 18  + 16 + 4 * 8 * 16 * 17) * 4;                  // 45312
    constexpr int SM_E3 = (16 * 9 * 4 * 18 + 32 + 8 * 16 * 8 * 9) * 4;                   // 78464
    // conv_up: sWA(CA*9*COUT) + bias + sWB2(CB*9*GP*(2*COUT_T+2)) + input
    constexpr int SM_D2 = (32 * 9 * 16 + 16 + 16 * 9 * 4 * 10
                           + 2 * (32 * 8 * 9 + 16 * 16 * 17)) * 4;                        // 94784
    constexpr int SM_D1 = (16 * 9 * 8 + 8 + 8 * 9 * 1 * 18
                           + 2 * (16 * 16 * 17 + 8 * 32 * 33)) * 4;                       // 112224

    cudaFuncSetAttribute((const void*)conv_std_k<8, 16, 8, 16, 4, 8, true>,
                         cudaFuncAttributeMaxDynamicSharedMemorySize, SM_E2);
    cudaFuncSetAttribute((const void*)conv_std_k<16, 32, 8, 8, 8, 8, true>,
                         cudaFuncAttributeMaxDynamicSharedMemorySize, SM_E3);
    cudaFuncSetAttribute((const void*)conv_up_k<32, 16, 16, 4, 16, 2, 8>,
                         cudaFuncAttributeMaxDynamicSharedMemorySize, SM_D2);
    cudaFuncSetAttribute((const void*)conv_up_k<16, 8, 8, 8, 32, 2, 8>,
                         cudaFuncAttributeMaxDynamicSharedMemorySize, SM_D1);

    // 1) permute
    permute_kernel<<<32 * 3 * 32, 256>>>(x, xt);
    // 2) e1 = relu(conv 3->8 @32)
    conv_std_k<3, 8, 8, 32, 2, 8, false><<<BT / 2, 256, SM_E1>>>(xt, ew1, eb1, e1);
    // 3) e2 = relu(conv pool(e1) 8->16 @16)
    conv_std_k<8, 16, 8, 16, 4, 8, true><<<BT / 4, 256, SM_E2>>>(e1, ew2, eb2, e2);
    // 4) e3 = relu(conv pool(e2) 16->32 @8)
    conv_std_k<16, 32, 8, 8, 8, 8, true><<<BT / 8, 256, SM_E3>>>(e2, ew3, eb3, e3);
    // 5) d2 = relu(conv [up(e3), e2] 48->16 @16)
    conv_up_k<32, 16, 16, 4, 16, 2, 8><<<BT / 2, 256, SM_D2>>>(e3, e2, dw2, db2, d2v);
    // 6) d1 = relu(conv [up(d2), e1] 24->8 @32)
    conv_up_k<16, 8, 8, 8, 32, 2, 8><<<BT / 2, 256, SM_D1>>>(d2v, e1, dw1, db1, d1v);
    // 7) masks + masked features
    mask_feat_kernel<<<(BT * 1024) / 256, 256>>>(d1v, xt, ow, ob, feat);
    // 8) h1 = relu(feat @ lw1 + lb1) via split-K x8
    sgemm1_k<<<dim3(4, BT / 256, SPLITS), 256>>>(feat, lw1, part);
    reduce8_relu_kernel<<<(BT * HID + 255) / 256, 256>>>(part, lb1, h1);
    // 9) h2 = relu(h1 @ lw2 + lb2)
    sgemm_k<64, 64, 16, 4, 4, true><<<dim3(4, BT / 64), 256>>>(BT, HID, HID, h1, lw2, lb2, h2);
    // 10) out = tanh(h2 @ lw3 + lb3)*16+16
    loc3_kernel<<<(BT * 4 + 255) / 256, 256>>>(h2, lw3, lb3, out);
}

// round 9
// speedup vs baseline: 1.1139x; 1.1139x over previous
#include <cuda_runtime.h>
#include <cuda_bf16.h>
#include <math.h>

#define BB 32
#define TT 64
#define BT 2048
#define HID 200
#define FEAT 6144
#define SPLITS 8

// -------------------- scratch (device globals; no allocs) --------------------
__device__ float g_xt  [BT * 3  * 1024];
__device__ float g_e1  [BT * 8  * 1024];
__device__ float g_e2  [BT * 16 * 256];
__device__ float g_e3  [BT * 32 * 64];
__device__ float g_d2  [BT * 16 * 256];
__device__ float g_feat[BT * FEAT];
__device__ float g_h1  [BT * HID];
__device__ float g_h2  [BT * HID];
__device__ float g_part[SPLITS * BT * HID];

// -------------------- permute [B,C,H,W,T] -> [B*T,C,H,W] --------------------
__global__ void permute_kernel(const float* __restrict__ x, float* __restrict__ xt) {
    int bidx = blockIdx.x;
    int h = bidx & 31;
    int c = (bidx >> 5) % 3;
    int b = bidx / 96;
    __shared__ float s[32][65];
    const float* src = x + (size_t)(((b * 3 + c) * 32 + h) * 32) * 64;
    for (int i = threadIdx.x; i < 2048; i += blockDim.x) {
        int w = i >> 6, t = i & 63;
        s[w][t] = src[i];
    }
    __syncthreads();
    for (int i = threadIdx.x; i < 2048; i += blockDim.x) {
        int t = i >> 5, w = i & 31;
        xt[((size_t)((b * 64 + t) * 3 + c) << 10) + (h << 5) + w] = s[w][t];
    }
}

// -------------------- standard conv3x3 (+optional 2x2 maxpool of input, +ReLU)
// SMEM: input rows padded to HS+1; weights transposed to [ci][kh][kw][co].
template<int CA, int COUT, int COUT_T, int HS, int NBT, int NPIX, bool POOL>
__global__ void __launch_bounds__(256, 2)
conv_std_k(const float* __restrict__ inA, const float* __restrict__ wgt,
           const float* __restrict__ bias, float* __restrict__ out)
{
    constexpr int GP   = COUT / COUT_T;
    constexpr int PXT  = HS * HS / NPIX;
    constexpr int HP   = HS + 1;
    constexpr int CSZ  = HS * HP;
    constexpr int ASZP = CA * CSZ;
    constexpr int WSZ  = COUT * CA * 9;
    extern __shared__ float sm[];
    float* sW  = sm;
    float* sBi = sW + WSZ;
    float* sIn = sBi + COUT;

    const int tid = threadIdx.x, NT = blockDim.x;
    const int bt0 = blockIdx.x * NBT;

    for (int i = tid; i < WSZ; i += NT) {
        int co = i % COUT;
        int rest = i / COUT;
        int ci = rest / 9, kk = rest % 9;
        sW[i] = wgt[(co * CA + ci) * 9 + kk];
    }
    for (int i = tid; i < COUT; i += NT) sBi[i] = bias[i];

    for (int i = tid; i < NBT * CA * HS * HS; i += NT) {
        int nn = i / (CA * HS * HS), rr = i % (CA * HS * HS);
        int c = rr / (HS * HS), pp = rr % (HS * HS);
        int hh = pp / HS, ww = pp % HS;
        float v;
        if (POOL) {
            const float* s = inA + (size_t)((bt0 + nn) * CA + c) * (4 * HS * HS)
                                 + (2 * hh) * (2 * HS) + 2 * ww;
            v = fmaxf(fmaxf(s[0], s[1]), fmaxf(s[2 * HS], s[2 * HS + 1]));
        } else {
            v = inA[(size_t)(bt0 + nn) * (CA * HS * HS) + rr];
        }
        sIn[nn * ASZP + c * CSZ + hh * HP + ww] = v;
    }
    __syncthreads();

    const int n   = tid / (GP * PXT);
    const int r   = tid % (GP * PXT);
    const int cog = r / PXT;
    const int p   = r % PXT;
    const int h   = p / (HS / NPIX);
    const int w0  = (p % (HS / NPIX)) * NPIX;
    const float* sI = sIn + n * ASZP;

    float acc[COUT_T][NPIX];
    #pragma unroll
    for (int co = 0; co < COUT_T; co++) {
        float b = sBi[cog * COUT_T + co];
        #pragma unroll
        for (int j = 0; j < NPIX; j++) acc[co][j] = b;
    }

    #pragma unroll 1
    for (int ci = 0; ci < CA; ci++) {
        const float* ch = sI + ci * CSZ;
        #pragma unroll
        for (int kh = 0; kh < 3; kh++) {
            int ih = h + kh - 1;
            bool rowok = (ih >= 0) && (ih < HS);
            float v[NPIX + 2];
            #pragma unroll
            for (int j = 0; j < NPIX + 2; j++) {
                int iw = w0 + j - 1;
                v[j] = (rowok && iw >= 0 && iw < HS) ? ch[ih * HP + iw] : 0.f;
            }
            const float* wr = sW + (ci * 9 + kh * 3) * COUT + cog * COUT_T;
            #pragma unroll
            for (int co = 0; co < COUT_T; co++) {
                float wa = wr[co], wb = wr[COUT + co], wc = wr[2 * COUT + co];
                #pragma unroll
                for (int j = 0; j < NPIX; j++)
                    acc[co][j] = fmaf(wa, v[j], fmaf(wb, v[j + 1], fmaf(wc, v[j + 2], acc[co][j])));
            }
        }
    }

    const int btn = bt0 + n;
    #pragma unroll
    for (int co = 0; co < COUT_T; co++) {
        float* op = out + (size_t)((btn * COUT + cog * COUT_T + co) * HS + h) * HS + w0;
        #pragma unroll
        for (int j = 0; j < NPIX; j += 4)
            *reinterpret_cast<float4*>(op + j) =
                make_float4(fmaxf(acc[co][j], 0.f), fmaxf(acc[co][j + 1], 0.f),
                            fmaxf(acc[co][j + 2], 0.f), fmaxf(acc[co][j + 3], 0.f));
    }
}

// -------------------- decoder conv3x3 over [up2x(A), B] (+opt fused mask) ----
// A at coarse HA=HS/2 (parity-folded 2x2 stencil), padded pitches, transposed W.
// FUSE (d1 only, requires GP==1, COUT==8, NPIX==8): instead of writing d1,
// compute 1x1-conv logits + softmax(w/ ones ch) in-register, multiply masks
// by xt, and write the 6144-wide feature tensor directly.
template<int CA, int CB, int COUT, int COUT_T, int HS, int NBT, int NPIX, bool FUSE>
__global__ void __launch_bounds__(256, 2)
conv_up_k(const float* __restrict__ inA, const float* __restrict__ inB,
          const float* __restrict__ wgt, const float* __restrict__ bias,
          const float* __restrict__ xtp, const float* __restrict__ owp,
          const float* __restrict__ obp, float* __restrict__ out)
{
    constexpr int CIN  = CA + CB;
    constexpr int HA   = HS / 2;
    constexpr int HAP  = HA + 1;
    constexpr int HP   = HS + 1;
    constexpr int CASZ = HA * HAP;
    constexpr int CBSZ = HS * HP;
    constexpr int ASZP = CA * CASZ;
    constexpr int TSZ  = ASZP + CB * CBSZ;
    constexpr int GP   = COUT / COUT_T;
    constexpr int PXT  = HS * HS / NPIX;
    constexpr int WSZ  = COUT * CIN * 9;
    constexpr int NC   = NPIX / 2 + 2;

    extern __shared__ float sm[];
    float* sW  = sm;                  // transposed [CIN*9][COUT]
    float* sBi = sW + WSZ;
    float* sOW = sBi + COUT;          // 18 floats: ow[16], ob[2]
    float* sIn = sOW + 18;

    const int tid = threadIdx.x, NT = blockDim.x;
    const int bt0 = blockIdx.x * NBT;

    for (int i = tid; i < WSZ; i += NT) {
        int co = i % COUT;
        int rest = i / COUT;
        int ci = rest / 9, kk = rest % 9;
        sW[i] = wgt[(co * CIN + ci) * 9 + kk];
    }
    for (int i = tid; i < COUT; i += NT) sBi[i] = bias[i];
    if (FUSE) {
        for (int i = tid; i < 18; i += NT) sOW[i] = (i < 16) ? owp[i] : obp[i - 16];
    }
    for (int i = tid; i < NBT * CA * HA * HA; i += NT) {
        int nn = i / (CA * HA * HA), rr = i % (CA * HA * HA);
        int c = rr / (HA * HA), pp = rr % (HA * HA);
        sIn[nn * TSZ + c * CASZ + (pp / HA) * HAP + (pp % HA)] =
            inA[(size_t)(bt0 + nn) * (CA * HA * HA) + rr];
    }
    for (int i = tid; i < NBT * CB * HS * HS; i += NT) {
        int nn = i / (CB * HS * HS), rr = i % (CB * HS * HS);
        int c = rr / (HS * HS), pp = rr % (HS * HS);
        sIn[nn * TSZ + ASZP + c * CBSZ + (pp / HS) * HP + (pp % HS)] =
            inB[(size_t)(bt0 + nn) * (CB * HS * HS) + rr];
    }
    __syncthreads();

    const int n   = tid / (GP * PXT);
    const int r   = tid % (GP * PXT);
    const int cog = r / PXT;
    const int p   = r % PXT;
    const int h   = p / (HS / NPIX);
    const int w0  = (p % (HS / NPIX)) * NPIX;
    const float* sI = sIn + n * TSZ;

    float acc[COUT_T][NPIX];
    #pragma unroll
    for (int co = 0; co < COUT_T; co++) {
        float b = sBi[cog * COUT_T + co];
        #pragma unroll
        for (int j = 0; j < NPIX; j++) acc[co][j] = b;
    }

    // ---- A part: coarse 2x2 stencil with parity-folded weights ----
    const int  a    = h >> 1;
    const bool hodd = (h & 1) != 0;
    const int  rowA = hodd ? a : a - 1;
    const int  rowB = hodd ? a + 1 : a;
    const int  cs0  = (w0 >> 1) - 1;

    #pragma unroll 1
    for (int ci = 0; ci < CA; ci++) {
        const float* ch = sI + ci * CASZ;
        float cAr[NC], cBr[NC];
        #pragma unroll
        for (int k = 0; k < NC; k++) {
            int cc = cs0 + k;
            bool cok = (cc >= 0) && (cc < HA);
            cAr[k] = (cok && rowA >= 0) ? ch[rowA * HAP + cc] : 0.f;
            cBr[k] = (cok && rowB < HA) ? ch[rowB * HAP + cc] : 0.f;
        }
        const float* wr = sW + ci * 9 * COUT + cog * COUT_T;
        #pragma unroll
        for (int co = 0; co < COUT_T; co++) {
            float w00 = wr[0 * COUT + co], w01 = wr[1 * COUT + co], w02 = wr[2 * COUT + co];
            float w10 = wr[3 * COUT + co], w11 = wr[4 * COUT + co], w12 = wr[5 * COUT + co];
            float w20 = wr[6 * COUT + co], w21 = wr[7 * COUT + co], w22 = wr[8 * COUT + co];
            float rA0 = hodd ? (w00 + w10) : w00;
            float rA1 = hodd ? (w01 + w11) : w01;
            float rA2 = hodd ? (w02 + w12) : w02;
            float rB0 = hodd ? w20 : (w10 + w20);
            float rB1 = hodd ? w21 : (w11 + w21);
            float rB2 = hodd ? w22 : (w12 + w22);
            float sA0 = rA0, sA01 = rA0 + rA1, sA12 = rA1 + rA2, sA2 = rA2;
            float sB0 = rB0, sB01 = rB0 + rB1, sB12 = rB1 + rB2, sB2 = rB2;
            #pragma unroll
            for (int j = 0; j < NPIX; j++) {
                int lb = (j >> 1) + 1;
                if ((j & 1) == 0) {
                    acc[co][j] = fmaf(cAr[lb - 1], sA0,  acc[co][j]);
                    acc[co][j] = fmaf(cAr[lb],     sA12, acc[co][j]);
                    acc[co][j] = fmaf(cBr[lb - 1], sB0,  acc[co][j]);
                    acc[co][j] = fmaf(cBr[lb],     sB12, acc[co][j]);
                } else {
                    acc[co][j] = fmaf(cAr[lb],     sA01, acc[co][j]);
                    acc[co][j] = fmaf(cAr[lb + 1], sA2,  acc[co][j]);
                    acc[co][j] = fmaf(cBr[lb],     sB01, acc[co][j]);
                    acc[co][j] = fmaf(cBr[lb + 1], sB2,  acc[co][j]);
                }
            }
        }
    }

    // ---- B part: standard fine 3x3 ----
    #pragma unroll 1
    for (int ci = 0; ci < CB; ci++) {
        const float* ch = sI + ASZP + ci * CBSZ;
        #pragma unroll
        for (int kh = 0; kh < 3; kh++) {
            int ih = h + kh - 1;
            bool rowok = (ih >= 0) && (ih < HS);
            float v[NPIX + 2];
            #pragma unroll
            for (int j = 0; j < NPIX + 2; j++) {
                int iw = w0 + j - 1;
                v[j] = (rowok && iw >= 0 && iw < HS) ? ch[ih * HP + iw] : 0.f;
            }
            const float* wr = sW + ((CA + ci) * 9 + kh * 3) * COUT + cog * COUT_T;
            #pragma unroll
            for (int co = 0; co < COUT_T; co++) {
                float wa = wr[co], wb = wr[COUT + co], wc = wr[2 * COUT + co];
                #pragma unroll
                for (int j = 0; j < NPIX; j++)
                    acc[co][j] = fmaf(wa, v[j], fmaf(wb, v[j + 1], fmaf(wc, v[j + 2], acc[co][j])));
            }
        }
    }

    const int btn = bt0 + n;
    if constexpr (FUSE) {
        // relu -> 1x1 conv logits -> softmax(with ones ch) -> masked features
        float m0a[NPIX], m1a[NPIX];
        #pragma unroll
        for (int j = 0; j < NPIX; j++) {
            float l0 = sOW[16], l1 = sOW[17];
            #pragma unroll
            for (int co = 0; co < COUT_T; co++) {
                float dv = fmaxf(acc[co][j], 0.f);
                l0 = fmaf(dv, sOW[co], l0);
                l1 = fmaf(dv, sOW[8 + co], l1);
            }
            float mx = fmaxf(fmaxf(l0, l1), 1.0f);
            float e0 = expf(l0 - mx), e1v = expf(l1 - mx), e2v = expf(1.0f - mx);
            float inv = 1.0f / (e0 + e1v + e2v);
            m0a[j] = e0 * inv;
            m1a[j] = e1v * inv;
        }
        const float* xp = xtp + ((size_t)btn * 3 << 10) + (h << 5) + w0;
        float* fp = out + (size_t)btn * FEAT + (h << 5) + w0;
        #pragma unroll
        for (int c = 0; c < 3; c++) {
            float4 xa = *reinterpret_cast<const float4*>(xp + ((size_t)c << 10));
            float4 xb = *reinterpret_cast<const float4*>(xp + ((size_t)c << 10) + 4);
            float* f0 = fp + ((size_t)c << 10);
            float* f1 = fp + ((size_t)(3 + c) << 10);
            *reinterpret_cast<float4*>(f0) =
                make_float4(m0a[0] * xa.x, m0a[1] * xa.y, m0a[2] * xa.z, m0a[3] * xa.w);
            *reinterpret_cast<float4*>(f0 + 4) =
                make_float4(m0a[4] * xb.x, m0a[5] * xb.y, m0a[6] * xb.z, m0a[7] * xb.w);
            *reinterpret_cast<float4*>(f1) =
                make_float4(m1a[0] * xa.x, m1a[1] * xa.y, m1a[2] * xa.z, m1a[3] * xa.w);
            *reinterpret_cast<float4*>(f1 + 4) =
                make_float4(m1a[4] * xb.x, m1a[5] * xb.y, m1a[6] * xb.z, m1a[7] * xb.w);
        }
    } else {
        #pragma unroll
        for (int co = 0; co < COUT_T; co++) {
            float* op = out + (size_t)((btn * COUT + cog * COUT_T + co) * HS + h) * HS + w0;
            #pragma unroll
            for (int j = 0; j < NPIX; j += 4)
                *reinterpret_cast<float4*>(op + j) =
                    make_float4(fmaxf(acc[co][j], 0.f), fmaxf(acc[co][j + 1], 0.f),
                                fmaxf(acc[co][j + 2], 0.f), fmaxf(acc[co][j + 3], 0.f));
        }
    }
}

// -------------------- GEMM1: split-K, BM256/BN64/BK16, TM16/TN4 --------------
__global__ void __launch_bounds__(256)
sgemm1_k(const float* __restrict__ A, const float* __restrict__ Bm,
         float* __restrict__ Cpart)
{
    constexpr int M = BT, N = HID, K = FEAT;
    constexpr int BM = 256, BN = 64, BK = 16;
    constexpr int KS = K / SPLITS;
    __shared__ float sA[BK][BM + 4];
    __shared__ float sB[BK][BN + 4];

    const int tid = threadIdx.x;
    const int tx = tid % 16;
    const int ty = tid / 16;
    const int bm = blockIdx.y * BM;
    const int bn = blockIdx.x * BN;
    const int kbase = blockIdx.z * KS;

    const int c4 = tid % 4;
    const int r0 = tid / 4;

    float acc[16][4];
    #pragma unroll
    for (int i = 0; i < 16; i++)
        #pragma unroll
        for (int j = 0; j < 4; j++) acc[i][j] = 0.f;

    for (int k0 = kbase; k0 < kbase + KS; k0 += BK) {
        #pragma unroll
        for (int q = 0; q < 4; q++) {
            int rr = r0 + 64 * q;
            float4 av = *reinterpret_cast<const float4*>(&A[(size_t)(bm + rr) * K + k0 + c4 * 4]);
            sA[c4 * 4 + 0][rr] = av.x;
            sA[c4 * 4 + 1][rr] = av.y;
            sA[c4 * 4 + 2][rr] = av.z;
            sA[c4 * 4 + 3][rr] = av.w;
        }
        {
            int kk = tid / 16;
            int cc = (tid % 16) * 4;
            int gcol = bn + cc;
            float4 bv;
            if (gcol + 3 < N) {
                bv = *reinterpret_cast<const float4*>(&Bm[(size_t)(k0 + kk) * N + gcol]);
            } else {
                bv.x = (gcol + 0 < N) ? Bm[(size_t)(k0 + kk) * N + gcol + 0] : 0.f;
                bv.y = (gcol + 1 < N) ? Bm[(size_t)(k0 + kk) * N + gcol + 1] : 0.f;
                bv.z = (gcol + 2 < N) ? Bm[(size_t)(k0 + kk) * N + gcol + 2] : 0.f;
                bv.w = (gcol + 3 < N) ? Bm[(size_t)(k0 + kk) * N + gcol + 3] : 0.f;
            }
            *reinterpret_cast<float4*>(&sB[kk][cc]) = bv;
        }
        __syncthreads();

        #pragma unroll
        for (int kk = 0; kk < BK; kk++) {
            float4 b = *reinterpret_cast<const float4*>(&sB[kk][tx * 4]);
            #pragma unroll
            for (int q = 0; q < 4; q++) {
                float4 a = *reinterpret_cast<const float4*>(&sA[kk][ty * 16 + q * 4]);
                acc[q * 4 + 0][0] = fmaf(a.x, b.x, acc[q * 4 + 0][0]);
                acc[q * 4 + 0][1] = fmaf(a.x, b.y, acc[q * 4 + 0][1]);
                acc[q * 4 + 0][2] = fmaf(a.x, b.z, acc[q * 4 + 0][2]);
                acc[q * 4 + 0][3] = fmaf(a.x, b.w, acc[q * 4 + 0][3]);
                acc[q * 4 + 1][0] = fmaf(a.y, b.x, acc[q * 4 + 1][0]);
                acc[q * 4 + 1][1] = fmaf(a.y, b.y, acc[q * 4 + 1][1]);
                acc[q * 4 + 1][2] = fmaf(a.y, b.z, acc[q * 4 + 1][2]);
                acc[q * 4 + 1][3] = fmaf(a.y, b.w, acc[q * 4 + 1][3]);
                acc[q * 4 + 2][0] = fmaf(a.z, b.x, acc[q * 4 + 2][0]);
                acc[q * 4 + 2][1] = fmaf(a.z, b.y, acc[q * 4 + 2][1]);
                acc[q * 4 + 2][2] = fmaf(a.z, b.z, acc[q * 4 + 2][2]);
                acc[q * 4 + 2][3] = fmaf(a.z, b.w, acc[q * 4 + 2][3]);
                acc[q * 4 + 3][0] = fmaf(a.w, b.x, acc[q * 4 + 3][0]);
                acc[q * 4 + 3][1] = fmaf(a.w, b.y, acc[q * 4 + 3][1]);
                acc[q * 4 + 3][2] = fmaf(a.w, b.z, acc[q * 4 + 3][2]);
                acc[q * 4 + 3][3] = fmaf(a.w, b.w, acc[q * 4 + 3][3]);
            }
        }
        __syncthreads();
    }

    float* Cp = Cpart + (size_t)blockIdx.z * M * N;
    #pragma unroll
    for (int i = 0; i < 16; i++) {
        int m = bm + ty * 16 + i;
        #pragma unroll
        for (int j = 0; j < 4; j++) {
            int n = bn + tx * 4 + j;
            if (n < N) Cp[(size_t)m * N + n] = acc[i][j];
        }
    }
}

__global__ void reduce8_relu_kernel(const float* __restrict__ part,
                                    const float* __restrict__ bias,
                                    float* __restrict__ out)
{
    int idx = blockIdx.x * blockDim.x + threadIdx.x;
    if (idx >= BT * HID) return;
    int n = idx % HID;
    float v = bias[n];
    #pragma unroll
    for (int s = 0; s < SPLITS; s++) v += part[(size_t)s * BT * HID + idx];
    out[idx] = fmaxf(v, 0.f);
}

// -------------------- tiled SGEMM (GEMM2, bias+relu) --------------------------
template<int BM, int BN, int BK, int TM, int TN, bool RELU>
__global__ void sgemm_k(int M, int N, int K,
                        const float* __restrict__ A, const float* __restrict__ Bm,
                        const float* __restrict__ bias, float* __restrict__ C)
{
    __shared__ float sA[BK][BM + 1];
    __shared__ float sB[BK][BN];
    const int tid = threadIdx.x;
    const int tx = tid % (BN / TN);
    const int ty = tid / (BN / TN);
    const int bm = blockIdx.y * BM;
    const int bn = blockIdx.x * BN;

    float acc[TM][TN];
    #pragma unroll
    for (int i = 0; i < TM; i++)
        #pragma unroll
        for (int j = 0; j < TN; j++) acc[i][j] = 0.f;

    for (int k0 = 0; k0 < K; k0 += BK) {
        for (int i = tid; i < BM * BK; i += 256) {
            int m = i / BK, kk = i % BK;
            sA[kk][m] = (bm + m < M && k0 + kk < K) ? A[(size_t)(bm + m) * K + k0 + kk] : 0.f;
        }
        for (int i = tid; i < BK * BN; i += 256) {
            int kk = i / BN, n = i % BN;
            sB[kk][n] = (k0 + kk < K && bn + n < N) ? Bm[(size_t)(k0 + kk) * N + bn + n] : 0.f;
        }
        __syncthreads();
        #pragma unroll
        for (int kk = 0; kk < BK; kk++) {
            float a[TM], b[TN];
            #pragma unroll
            for (int i = 0; i < TM; i++) a[i] = sA[kk][ty * TM + i];
            #pragma unroll
            for (int j = 0; j < TN; j++) b[j] = sB[kk][tx * TN + j];
            #pragma unroll
            for (int i = 0; i < TM; i++)
                #pragma unroll
                for (int j = 0; j < TN; j++) acc[i][j] = fmaf(a[i], b[j], acc[i][j]);
        }
        __syncthreads();
    }

    #pragma unroll
    for (int i = 0; i < TM; i++) {
        int m = bm + ty * TM + i;
        if (m >= M) continue;
        #pragma unroll
        for (int j = 0; j < TN; j++) {
            int n = bn + tx * TN + j;
            if (n >= N) continue;
            float v = acc[i][j] + bias[n];
            if (RELU) v = fmaxf(v, 0.f);
            C[(size_t)m * N + n] = v;
        }
    }
}

// -------------------- final 200->4 + tanh scale ------------------------------
__global__ void loc3_kernel(const float* __restrict__ h2, const float* __restrict__ w3,
                            const float* __restrict__ b3, float* __restrict__ out)
{
    int idx = blockIdx.x * blockDim.x + threadIdx.x;
    if (idx >= BT * 4) return;
    int m = idx >> 2, j = idx & 3;
    float acc = b3[j];
    const float* hp = h2 + (size_t)m * HID;
    #pragma unroll 8
    for (int k = 0; k < HID; k++) acc = fmaf(hp[k], w3[k * 4 + j], acc);
    out[idx] = tanhf(acc) * 16.f + 16.f;
}

// -------------------- launch --------------------------------------------------
extern "C" void kernel_launch(void* const* d_in, const int* in_sizes, int n_in,
                              void* d_out, int out_size)
{
    const float* x   = (const float*)d_in[0];
    const float* ew1 = (const float*)d_in[1];
    const float* eb1 = (const float*)d_in[2];
    const float* ew2 = (const float*)d_in[3];
    const float* eb2 = (const float*)d_in[4];
    const float* ew3 = (const float*)d_in[5];
    const float* eb3 = (const float*)d_in[6];
    const float* dw2 = (const float*)d_in[7];
    const float* db2 = (const float*)d_in[8];
    const float* dw1 = (const float*)d_in[9];
    const float* db1 = (const float*)d_in[10];
    const float* ow  = (const float*)d_in[11];
    const float* ob  = (const float*)d_in[12];
    const float* lw1 = (const float*)d_in[13];
    const float* lb1 = (const float*)d_in[14];
    const float* lw2 = (const float*)d_in[15];
    const float* lb2 = (const float*)d_in[16];
    const float* lw3 = (const float*)d_in[17];
    const float* lb3 = (const float*)d_in[18];
    float* out = (float*)d_out;

    float *xt, *e1, *e2, *e3, *d2v, *feat, *h1, *h2, *part;
    cudaGetSymbolAddress((void**)&xt,   g_xt);
    cudaGetSymbolAddress((void**)&e1,   g_e1);
    cudaGetSymbolAddress((void**)&e2,   g_e2);
    cudaGetSymbolAddress((void**)&e3,   g_e3);
    cudaGetSymbolAddress((void**)&d2v,  g_d2);
    cudaGetSymbolAddress((void**)&feat, g_feat);
    cudaGetSymbolAddress((void**)&h1,   g_h1);
    cudaGetSymbolAddress((void**)&h2,   g_h2);
    cudaGetSymbolAddress((void**)&part, g_part);

    // smem bytes (R3-proven padded layouts; conv_up +18 floats for ow/ob)
    constexpr int SM_E1 = (3 * 8 * 9  + 8  + 2 * 3 * 32 * 33) * 4;                         // 26240
    constexpr int SM_E2 = (8 * 16 * 9 + 16 + 4 * 8 * 16 * 17) * 4;                         // 39488
    constexpr int SM_E3 = (16 * 32 * 9 + 32 + 8 * 16 * 8 * 9) * 4;                         // 55424
    constexpr int SM_D2 = (48 * 16 * 9 + 16 + 18 + 2 * (32 * 8 * 9 + 16 * 16 * 17)) * 4;   // 81032
    constexpr int SM_D1 = (24 * 8 * 9 + 8 + 18 + 2 * (16 * 16 * 17 + 8 * 32 * 33)) * 4;    // 109416

    cudaFuncSetAttribute((const void*)conv_std_k<8, 16, 8, 16, 4, 8, true>,
                         cudaFuncAttributeMaxDynamicSharedMemorySize, SM_E2);
    cudaFuncSetAttribute((const void*)conv_std_k<16, 32, 8, 8, 8, 8, true>,
                         cudaFuncAttributeMaxDynamicSharedMemorySize, SM_E3);
    cudaFuncSetAttribute((const void*)conv_up_k<32, 16, 16, 4, 16, 2, 8, false>,
                         cudaFuncAttributeMaxDynamicSharedMemorySize, SM_D2);
    cudaFuncSetAttribute((const void*)conv_up_k<16, 8, 8, 8, 32, 2, 8, true>,
                         cudaFuncAttributeMaxDynamicSharedMemorySize, SM_D1);

    // 1) permute
    permute_kernel<<<32 * 3 * 32, 256>>>(x, xt);
    // 2) e1 = relu(conv 3->8 @32)
    conv_std_k<3, 8, 8, 32, 2, 8, false><<<BT / 2, 256, SM_E1>>>(xt, ew1, eb1, e1);
    // 3) e2 = relu(conv pool(e1) 8->16 @16)
    conv_std_k<8, 16, 8, 16, 4, 8, true><<<BT / 4, 256, SM_E2>>>(e1, ew2, eb2, e2);
    // 4) e3 = relu(conv pool(e2) 16->32 @8)
    conv_std_k<16, 32, 8, 8, 8, 8, true><<<BT / 8, 256, SM_E3>>>(e2, ew3, eb3, e3);
    // 5) d2 = relu(conv [up(e3), e2] 48->16 @16)
    conv_up_k<32, 16, 16, 4, 16, 2, 8, false><<<BT / 2, 256, SM_D2>>>(
        e3, e2, dw2, db2, nullptr, nullptr, nullptr, d2v);
    // 6) d1 conv + 1x1 + softmax + masked features, fused -> feat
    conv_up_k<16, 8, 8, 8, 32, 2, 8, true><<<BT / 2, 256, SM_D1>>>(
        d2v, e1, dw1, db1, xt, ow, ob, feat);
    // 7) h1 = relu(feat @ lw1 + lb1) via split-K x8
    sgemm1_k<<<dim3(4, BT / 256, SPLITS), 256>>>(feat, lw1, part);
    reduce8_relu_kernel<<<(BT * HID + 255) / 256, 256>>>(part, lb1, h1);
    // 8) h2 = relu(h1 @ lw2 + lb2)
    sgemm_k<64, 64, 16, 4, 4, true><<<dim3(4, BT / 64), 256>>>(BT, HID, HID, h1, lw2, lb2, h2);
    // 9) out = tanh(h2 @ lw3 + lb3)*16+16
    loc3_kernel<<<(BT * 4 + 255) / 256, 256>>>(h2, lw3, lb3, out);
}

// round 10
// speedup vs baseline: 1.1909x; 1.0691x over previous
#include <cuda_runtime.h>
#include <cuda_bf16.h>
#include <math.h>

#define BB 32
#define TT 64
#define BT 2048
#define HID 200
#define FEAT 6144
#define SPLITS 8

// -------------------- scratch (device globals; no allocs) --------------------
__device__ float g_xt  [BT * 3  * 1024];
__device__ float g_e1  [BT * 8  * 1024];
__device__ float g_e2  [BT * 16 * 256];
__device__ float g_e3  [BT * 32 * 64];
__device__ float g_d2  [BT * 16 * 256];
__device__ float g_feat[BT * FEAT];
__device__ float g_h2  [BT * HID];
__device__ float g_part[SPLITS * BT * HID];

// -------------------- permute [B,C,H,W,T] -> [B*T,C,H,W] --------------------
__global__ void permute_kernel(const float* __restrict__ x, float* __restrict__ xt) {
    int bidx = blockIdx.x;
    int h = bidx & 31;
    int c = (bidx >> 5) % 3;
    int b = bidx / 96;
    __shared__ float s[32][65];
    const float* src = x + (size_t)(((b * 3 + c) * 32 + h) * 32) * 64;
    for (int i = threadIdx.x; i < 2048; i += blockDim.x) {
        int w = i >> 6, t = i & 63;
        s[w][t] = src[i];
    }
    __syncthreads();
    for (int i = threadIdx.x; i < 2048; i += blockDim.x) {
        int t = i >> 5, w = i & 31;
        xt[((size_t)((b * 64 + t) * 3 + c) << 10) + (h << 5) + w] = s[w][t];
    }
}

// -------------------- standard conv3x3 (+optional 2x2 maxpool of input, +ReLU)
// SMEM: input rows padded to HS+1; weights transposed to [ci][kh][kw][co].
// Tile fill uses float4 global loads (fine) / paired float4 loads (pooled).
template<int CA, int COUT, int COUT_T, int HS, int NBT, int NPIX, bool POOL>
__global__ void __launch_bounds__(256, 2)
conv_std_k(const float* __restrict__ inA, const float* __restrict__ wgt,
           const float* __restrict__ bias, float* __restrict__ out)
{
    constexpr int GP   = COUT / COUT_T;
    constexpr int PXT  = HS * HS / NPIX;
    constexpr int HP   = HS + 1;
    constexpr int CSZ  = HS * HP;
    constexpr int ASZP = CA * CSZ;
    constexpr int WSZ  = COUT * CA * 9;
    extern __shared__ float sm[];
    float* sW  = sm;
    float* sBi = sW + WSZ;
    float* sIn = sBi + COUT;

    const int tid = threadIdx.x, NT = blockDim.x;
    const int bt0 = blockIdx.x * NBT;

    for (int i = tid; i < WSZ; i += NT) {
        int co = i % COUT;
        int rest = i / COUT;
        int ci = rest / 9, kk = rest % 9;
        sW[i] = wgt[(co * CA + ci) * 9 + kk];
    }
    for (int i = tid; i < COUT; i += NT) sBi[i] = bias[i];

    if (POOL) {
        // paired pooled load: 2 float4 reads -> 2 pooled outputs
        for (int i = tid; i < NBT * CA * HS * HS / 2; i += NT) {
            int e2 = i * 2;
            int nn = e2 / (CA * HS * HS), rr = e2 % (CA * HS * HS);
            int c = rr / (HS * HS), pp = rr % (HS * HS);
            int hh = pp / HS, ww = pp % HS;                 // ww even
            const float* s = inA + (size_t)((bt0 + nn) * CA + c) * (4 * HS * HS)
                                 + (2 * hh) * (2 * HS) + 2 * ww;
            float4 r0 = *reinterpret_cast<const float4*>(s);
            float4 r1 = *reinterpret_cast<const float4*>(s + 2 * HS);
            float* d = sIn + nn * ASZP + c * CSZ + hh * HP + ww;
            d[0] = fmaxf(fmaxf(r0.x, r0.y), fmaxf(r1.x, r1.y));
            d[1] = fmaxf(fmaxf(r0.z, r0.w), fmaxf(r1.z, r1.w));
        }
    } else {
        for (int i = tid; i < NBT * CA * HS * HS / 4; i += NT) {
            int e4 = i * 4;
            int nn = e4 / (CA * HS * HS), rr = e4 % (CA * HS * HS);
            int c = rr / (HS * HS), pp = rr % (HS * HS);
            int hh = pp / HS, ww = pp % HS;                 // ww mult of 4
            float4 v = *reinterpret_cast<const float4*>(
                inA + (size_t)(bt0 + nn) * (CA * HS * HS) + rr);
            float* d = sIn + nn * ASZP + c * CSZ + hh * HP + ww;
            d[0] = v.x; d[1] = v.y; d[2] = v.z; d[3] = v.w;
        }
    }
    __syncthreads();

    const int n   = tid / (GP * PXT);
    const int r   = tid % (GP * PXT);
    const int cog = r / PXT;
    const int p   = r % PXT;
    const int h   = p / (HS / NPIX);
    const int w0  = (p % (HS / NPIX)) * NPIX;
    const float* sI = sIn + n * ASZP;

    float acc[COUT_T][NPIX];
    #pragma unroll
    for (int co = 0; co < COUT_T; co++) {
        float b = sBi[cog * COUT_T + co];
        #pragma unroll
        for (int j = 0; j < NPIX; j++) acc[co][j] = b;
    }

    #pragma unroll 1
    for (int ci = 0; ci < CA; ci++) {
        const float* ch = sI + ci * CSZ;
        #pragma unroll
        for (int kh = 0; kh < 3; kh++) {
            int ih = h + kh - 1;
            bool rowok = (ih >= 0) && (ih < HS);
            float v[NPIX + 2];
            #pragma unroll
            for (int j = 0; j < NPIX + 2; j++) {
                int iw = w0 + j - 1;
                v[j] = (rowok && iw >= 0 && iw < HS) ? ch[ih * HP + iw] : 0.f;
            }
            const float* wr = sW + (ci * 9 + kh * 3) * COUT + cog * COUT_T;
            #pragma unroll
            for (int co = 0; co < COUT_T; co++) {
                float wa = wr[co], wb = wr[COUT + co], wc = wr[2 * COUT + co];
                #pragma unroll
                for (int j = 0; j < NPIX; j++)
                    acc[co][j] = fmaf(wa, v[j], fmaf(wb, v[j + 1], fmaf(wc, v[j + 2], acc[co][j])));
            }
        }
    }

    const int btn = bt0 + n;
    #pragma unroll
    for (int co = 0; co < COUT_T; co++) {
        float* op = out + (size_t)((btn * COUT + cog * COUT_T + co) * HS + h) * HS + w0;
        #pragma unroll
        for (int j = 0; j < NPIX; j += 4)
            *reinterpret_cast<float4*>(op + j) =
                make_float4(fmaxf(acc[co][j], 0.f), fmaxf(acc[co][j + 1], 0.f),
                            fmaxf(acc[co][j + 2], 0.f), fmaxf(acc[co][j + 3], 0.f));
    }
}

// -------------------- decoder conv3x3 over [up2x(A), B] (+opt fused mask) ----
// A at coarse HA=HS/2 (parity-folded 2x2 stencil), padded pitches, transposed W.
// float4 tile loads. FUSE (d1): 1x1-conv logits + softmax + masked feat -> out.
template<int CA, int CB, int COUT, int COUT_T, int HS, int NBT, int NPIX, bool FUSE>
__global__ void __launch_bounds__(256, 2)
conv_up_k(const float* __restrict__ inA, const float* __restrict__ inB,
          const float* __restrict__ wgt, const float* __restrict__ bias,
          const float* __restrict__ xtp, const float* __restrict__ owp,
          const float* __restrict__ obp, float* __restrict__ out)
{
    constexpr int CIN  = CA + CB;
    constexpr int HA   = HS / 2;
    constexpr int HAP  = HA + 1;
    constexpr int HP   = HS + 1;
    constexpr int CASZ = HA * HAP;
    constexpr int CBSZ = HS * HP;
    constexpr int ASZP = CA * CASZ;
    constexpr int TSZ  = ASZP + CB * CBSZ;
    constexpr int GP   = COUT / COUT_T;
    constexpr int PXT  = HS * HS / NPIX;
    constexpr int WSZ  = COUT * CIN * 9;
    constexpr int NC   = NPIX / 2 + 2;

    extern __shared__ float sm[];
    float* sW  = sm;                  // transposed [CIN*9][COUT]
    float* sBi = sW + WSZ;
    float* sOW = sBi + COUT;          // 18 floats: ow[16], ob[2]
    float* sIn = sOW + 18;

    const int tid = threadIdx.x, NT = blockDim.x;
    const int bt0 = blockIdx.x * NBT;

    for (int i = tid; i < WSZ; i += NT) {
        int co = i % COUT;
        int rest = i / COUT;
        int ci = rest / 9, kk = rest % 9;
        sW[i] = wgt[(co * CIN + ci) * 9 + kk];
    }
    for (int i = tid; i < COUT; i += NT) sBi[i] = bias[i];
    if (FUSE) {
        for (int i = tid; i < 18; i += NT) sOW[i] = (i < 16) ? owp[i] : obp[i - 16];
    }
    for (int i = tid; i < NBT * CA * HA * HA / 4; i += NT) {
        int e4 = i * 4;
        int nn = e4 / (CA * HA * HA), rr = e4 % (CA * HA * HA);
        int c = rr / (HA * HA), pp = rr % (HA * HA);
        float4 v = *reinterpret_cast<const float4*>(
            inA + (size_t)(bt0 + nn) * (CA * HA * HA) + rr);
        float* d = sIn + nn * TSZ + c * CASZ + (pp / HA) * HAP + (pp % HA);
        d[0] = v.x; d[1] = v.y; d[2] = v.z; d[3] = v.w;
    }
    for (int i = tid; i < NBT * CB * HS * HS / 4; i += NT) {
        int e4 = i * 4;
        int nn = e4 / (CB * HS * HS), rr = e4 % (CB * HS * HS);
        int c = rr / (HS * HS), pp = rr % (HS * HS);
        float4 v = *reinterpret_cast<const float4*>(
            inB + (size_t)(bt0 + nn) * (CB * HS * HS) + rr);
        float* d = sIn + nn * TSZ + ASZP + c * CBSZ + (pp / HS) * HP + (pp % HS);
        d[0] = v.x; d[1] = v.y; d[2] = v.z; d[3] = v.w;
    }
    __syncthreads();

    const int n   = tid / (GP * PXT);
    const int r   = tid % (GP * PXT);
    const int cog = r / PXT;
    const int p   = r % PXT;
    const int h   = p / (HS / NPIX);
    const int w0  = (p % (HS / NPIX)) * NPIX;
    const float* sI = sIn + n * TSZ;

    float acc[COUT_T][NPIX];
    #pragma unroll
    for (int co = 0; co < COUT_T; co++) {
        float b = sBi[cog * COUT_T + co];
        #pragma unroll
        for (int j = 0; j < NPIX; j++) acc[co][j] = b;
    }

    // ---- A part: coarse 2x2 stencil with parity-folded weights ----
    const int  a    = h >> 1;
    const bool hodd = (h & 1) != 0;
    const int  rowA = hodd ? a : a - 1;
    const int  rowB = hodd ? a + 1 : a;
    const int  cs0  = (w0 >> 1) - 1;

    #pragma unroll 1
    for (int ci = 0; ci < CA; ci++) {
        const float* ch = sI + ci * CASZ;
        float cAr[NC], cBr[NC];
        #pragma unroll
        for (int k = 0; k < NC; k++) {
            int cc = cs0 + k;
            bool cok = (cc >= 0) && (cc < HA);
            cAr[k] = (cok && rowA >= 0) ? ch[rowA * HAP + cc] : 0.f;
            cBr[k] = (cok && rowB < HA) ? ch[rowB * HAP + cc] : 0.f;
        }
        const float* wr = sW + ci * 9 * COUT + cog * COUT_T;
        #pragma unroll
        for (int co = 0; co < COUT_T; co++) {
            float w00 = wr[0 * COUT + co], w01 = wr[1 * COUT + co], w02 = wr[2 * COUT + co];
            float w10 = wr[3 * COUT + co], w11 = wr[4 * COUT + co], w12 = wr[5 * COUT + co];
            float w20 = wr[6 * COUT + co], w21 = wr[7 * COUT + co], w22 = wr[8 * COUT + co];
            float rA0 = hodd ? (w00 + w10) : w00;
            float rA1 = hodd ? (w01 + w11) : w01;
            float rA2 = hodd ? (w02 + w12) : w02;
            float rB0 = hodd ? w20 : (w10 + w20);
            float rB1 = hodd ? w21 : (w11 + w21);
            float rB2 = hodd ? w22 : (w12 + w22);
            float sA0 = rA0, sA01 = rA0 + rA1, sA12 = rA1 + rA2, sA2 = rA2;
            float sB0 = rB0, sB01 = rB0 + rB1, sB12 = rB1 + rB2, sB2 = rB2;
            #pragma unroll
            for (int j = 0; j < NPIX; j++) {
                int lb = (j >> 1) + 1;
                if ((j & 1) == 0) {
                    acc[co][j] = fmaf(cAr[lb - 1], sA0,  acc[co][j]);
                    acc[co][j] = fmaf(cAr[lb],     sA12, acc[co][j]);
                    acc[co][j] = fmaf(cBr[lb - 1], sB0,  acc[co][j]);
                    acc[co][j] = fmaf(cBr[lb],     sB12, acc[co][j]);
                } else {
                    acc[co][j] = fmaf(cAr[lb],     sA01, acc[co][j]);
                    acc[co][j] = fmaf(cAr[lb + 1], sA2,  acc[co][j]);
                    acc[co][j] = fmaf(cBr[lb],     sB01, acc[co][j]);
                    acc[co][j] = fmaf(cBr[lb + 1], sB2,  acc[co][j]);
                }
            }
        }
    }

    // ---- B part: standard fine 3x3 ----
    #pragma unroll 1
    for (int ci = 0; ci < CB; ci++) {
        const float* ch = sI + ASZP + ci * CBSZ;
        #pragma unroll
        for (int kh = 0; kh < 3; kh++) {
            int ih = h + kh - 1;
            bool rowok = (ih >= 0) && (ih < HS);
            float v[NPIX + 2];
            #pragma unroll
            for (int j = 0; j < NPIX + 2; j++) {
                int iw = w0 + j - 1;
                v[j] = (rowok && iw >= 0 && iw < HS) ? ch[ih * HP + iw] : 0.f;
            }
            const float* wr = sW + ((CA + ci) * 9 + kh * 3) * COUT + cog * COUT_T;
            #pragma unroll
            for (int co = 0; co < COUT_T; co++) {
                float wa = wr[co], wb = wr[COUT + co], wc = wr[2 * COUT + co];
                #pragma unroll
                for (int j = 0; j < NPIX; j++)
                    acc[co][j] = fmaf(wa, v[j], fmaf(wb, v[j + 1], fmaf(wc, v[j + 2], acc[co][j])));
            }
        }
    }

    const int btn = bt0 + n;
    if constexpr (FUSE) {
        float m0a[NPIX], m1a[NPIX];
        #pragma unroll
        for (int j = 0; j < NPIX; j++) {
            float l0 = sOW[16], l1 = sOW[17];
            #pragma unroll
            for (int co = 0; co < COUT_T; co++) {
                float dv = fmaxf(acc[co][j], 0.f);
                l0 = fmaf(dv, sOW[co], l0);
                l1 = fmaf(dv, sOW[8 + co], l1);
            }
            float mx = fmaxf(fmaxf(l0, l1), 1.0f);
            float e0 = expf(l0 - mx), e1v = expf(l1 - mx), e2v = expf(1.0f - mx);
            float inv = 1.0f / (e0 + e1v + e2v);
            m0a[j] = e0 * inv;
            m1a[j] = e1v * inv;
        }
        const float* xp = xtp + ((size_t)btn * 3 << 10) + (h << 5) + w0;
        float* fp = out + (size_t)btn * FEAT + (h << 5) + w0;
        #pragma unroll
        for (int c = 0; c < 3; c++) {
            float4 xa = *reinterpret_cast<const float4*>(xp + ((size_t)c << 10));
            float4 xb = *reinterpret_cast<const float4*>(xp + ((size_t)c << 10) + 4);
            float* f0 = fp + ((size_t)c << 10);
            float* f1 = fp + ((size_t)(3 + c) << 10);
            *reinterpret_cast<float4*>(f0) =
                make_float4(m0a[0] * xa.x, m0a[1] * xa.y, m0a[2] * xa.z, m0a[3] * xa.w);
            *reinterpret_cast<float4*>(f0 + 4) =
                make_float4(m0a[4] * xb.x, m0a[5] * xb.y, m0a[6] * xb.z, m0a[7] * xb.w);
            *reinterpret_cast<float4*>(f1) =
                make_float4(m1a[0] * xa.x, m1a[1] * xa.y, m1a[2] * xa.z, m1a[3] * xa.w);
            *reinterpret_cast<float4*>(f1 + 4) =
                make_float4(m1a[4] * xb.x, m1a[5] * xb.y, m1a[6] * xb.z, m1a[7] * xb.w);
        }
    } else {
        #pragma unroll
        for (int co = 0; co < COUT_T; co++) {
            float* op = out + (size_t)((btn * COUT + cog * COUT_T + co) * HS + h) * HS + w0;
            #pragma unroll
            for (int j = 0; j < NPIX; j += 4)
                *reinterpret_cast<float4*>(op + j) =
                    make_float4(fmaxf(acc[co][j], 0.f), fmaxf(acc[co][j + 1], 0.f),
                                fmaxf(acc[co][j + 2], 0.f), fmaxf(acc[co][j + 3], 0.f));
        }
    }
}

// -------------------- GEMM1: split-K, BM256/BN64/BK16, TM16/TN4 --------------
__global__ void __launch_bounds__(256)
sgemm1_k(const float* __restrict__ A, const float* __restrict__ Bm,
         float* __restrict__ Cpart)
{
    constexpr int M = BT, N = HID, K = FEAT;
    constexpr int BM = 256, BN = 64, BK = 16;
    constexpr int KS = K / SPLITS;
    __shared__ float sA[BK][BM + 4];
    __shared__ float sB[BK][BN + 4];

    const int tid = threadIdx.x;
    const int tx = tid % 16;
    const int ty = tid / 16;
    const int bm = blockIdx.y * BM;
    const int bn = blockIdx.x * BN;
    const int kbase = blockIdx.z * KS;

    const int c4 = tid % 4;
    const int r0 = tid / 4;

    float acc[16][4];
    #pragma unroll
    for (int i = 0; i < 16; i++)
        #pragma unroll
        for (int j = 0; j < 4; j++) acc[i][j] = 0.f;

    for (int k0 = kbase; k0 < kbase + KS; k0 += BK) {
        #pragma unroll
        for (int q = 0; q < 4; q++) {
            int rr = r0 + 64 * q;
            float4 av = *reinterpret_cast<const float4*>(&A[(size_t)(bm + rr) * K + k0 + c4 * 4]);
            sA[c4 * 4 + 0][rr] = av.x;
            sA[c4 * 4 + 1][rr] = av.y;
            sA[c4 * 4 + 2][rr] = av.z;
            sA[c4 * 4 + 3][rr] = av.w;
        }
        {
            int kk = tid / 16;
            int cc = (tid % 16) * 4;
            int gcol = bn + cc;
            float4 bv;
            if (gcol + 3 < N) {
                bv = *reinterpret_cast<const float4*>(&Bm[(size_t)(k0 + kk) * N + gcol]);
            } else {
                bv.x = (gcol + 0 < N) ? Bm[(size_t)(k0 + kk) * N + gcol + 0] : 0.f;
                bv.y = (gcol + 1 < N) ? Bm[(size_t)(k0 + kk) * N + gcol + 1] : 0.f;
                bv.z = (gcol + 2 < N) ? Bm[(size_t)(k0 + kk) * N + gcol + 2] : 0.f;
                bv.w = (gcol + 3 < N) ? Bm[(size_t)(k0 + kk) * N + gcol + 3] : 0.f;
            }
            *reinterpret_cast<float4*>(&sB[kk][cc]) = bv;
        }
        __syncthreads();

        #pragma unroll
        for (int kk = 0; kk < BK; kk++) {
            float4 b = *reinterpret_cast<const float4*>(&sB[kk][tx * 4]);
            #pragma unroll
            for (int q = 0; q < 4; q++) {
                float4 a = *reinterpret_cast<const float4*>(&sA[kk][ty * 16 + q * 4]);
                acc[q * 4 + 0][0] = fmaf(a.x, b.x, acc[q * 4 + 0][0]);
                acc[q * 4 + 0][1] = fmaf(a.x, b.y, acc[q * 4 + 0][1]);
                acc[q * 4 + 0][2] = fmaf(a.x, b.z, acc[q * 4 + 0][2]);
                acc[q * 4 + 0][3] = fmaf(a.x, b.w, acc[q * 4 + 0][3]);
                acc[q * 4 + 1][0] = fmaf(a.y, b.x, acc[q * 4 + 1][0]);
                acc[q * 4 + 1][1] = fmaf(a.y, b.y, acc[q * 4 + 1][1]);
                acc[q * 4 + 1][2] = fmaf(a.y, b.z, acc[q * 4 + 1][2]);
                acc[q * 4 + 1][3] = fmaf(a.y, b.w, acc[q * 4 + 1][3]);
                acc[q * 4 + 2][0] = fmaf(a.z, b.x, acc[q * 4 + 2][0]);
                acc[q * 4 + 2][1] = fmaf(a.z, b.y, acc[q * 4 + 2][1]);
                acc[q * 4 + 2][2] = fmaf(a.z, b.z, acc[q * 4 + 2][2]);
                acc[q * 4 + 2][3] = fmaf(a.z, b.w, acc[q * 4 + 2][3]);
                acc[q * 4 + 3][0] = fmaf(a.w, b.x, acc[q * 4 + 3][0]);
                acc[q * 4 + 3][1] = fmaf(a.w, b.y, acc[q * 4 + 3][1]);
                acc[q * 4 + 3][2] = fmaf(a.w, b.z, acc[q * 4 + 3][2]);
                acc[q * 4 + 3][3] = fmaf(a.w, b.w, acc[q * 4 + 3][3]);
            }
        }
        __syncthreads();
    }

    float* Cp = Cpart + (size_t)blockIdx.z * M * N;
    #pragma unroll
    for (int i = 0; i < 16; i++) {
        int m = bm + ty * 16 + i;
        #pragma unroll
        for (int j = 0; j < 4; j++) {
            int n = bn + tx * 4 + j;
            if (n < N) Cp[(size_t)m * N + n] = acc[i][j];
        }
    }
}

// -------------------- GEMM2 with fused split-K reduce of h1 ------------------
// A[m,k] = relu(lb1[k] + sum_s part[s][m][k]); C = relu? no: h2 = relu(A@lw2+lb2)
__global__ void __launch_bounds__(256)
sgemm2_k(const float* __restrict__ part, const float* __restrict__ ab,
         const float* __restrict__ Bm, const float* __restrict__ bias,
         float* __restrict__ C)
{
    constexpr int M = BT, N = HID, K = HID;
    constexpr int BM = 64, BN = 64, BK = 16;
    __shared__ float sA[BK][BM + 1];
    __shared__ float sB[BK][BN];
    const int tid = threadIdx.x;
    const int tx = tid % 16;
    const int ty = tid / 16;
    const int bm = blockIdx.y * BM;
    const int bn = blockIdx.x * BN;

    float acc[4][4];
    #pragma unroll
    for (int i = 0; i < 4; i++)
        #pragma unroll
        for (int j = 0; j < 4; j++) acc[i][j] = 0.f;

    for (int k0 = 0; k0 < K; k0 += BK) {
        for (int i = tid; i < BM * BK; i += 256) {
            int m = i / BK, kk = i % BK;
            float v = 0.f;
            if (k0 + kk < K) {
                size_t off = (size_t)(bm + m) * K + k0 + kk;
                float t = ab[k0 + kk];
                #pragma unroll
                for (int s = 0; s < SPLITS; s++) t += part[(size_t)s * M * K + off];
                v = fmaxf(t, 0.f);
            }
            sA[kk][m] = v;
        }
        for (int i = tid; i < BK * BN; i += 256) {
            int kk = i / BN, n = i % BN;
            sB[kk][n] = (k0 + kk < K && bn + n < N) ? Bm[(size_t)(k0 + kk) * N + bn + n] : 0.f;
        }
        __syncthreads();
        #pragma unroll
        for (int kk = 0; kk < BK; kk++) {
            float a[4], b[4];
            #pragma unroll
            for (int i = 0; i < 4; i++) a[i] = sA[kk][ty * 4 + i];
            #pragma unroll
            for (int j = 0; j < 4; j++) b[j] = sB[kk][tx * 4 + j];
            #pragma unroll
            for (int i = 0; i < 4; i++)
                #pragma unroll
                for (int j = 0; j < 4; j++) acc[i][j] = fmaf(a[i], b[j], acc[i][j]);
        }
        __syncthreads();
    }

    #pragma unroll
    for (int i = 0; i < 4; i++) {
        int m = bm + ty * 4 + i;
        #pragma unroll
        for (int j = 0; j < 4; j++) {
            int n = bn + tx * 4 + j;
            if (n >= N) continue;
            C[(size_t)m * N + n] = fmaxf(acc[i][j] + bias[n], 0.f);
        }
    }
}

// -------------------- final 200->4 + tanh scale ------------------------------
__global__ void loc3_kernel(const float* __restrict__ h2, const float* __restrict__ w3,
                            const float* __restrict__ b3, float* __restrict__ out)
{
    int idx = blockIdx.x * blockDim.x + threadIdx.x;
    if (idx >= BT * 4) return;
    int m = idx >> 2, j = idx & 3;
    float acc = b3[j];
    const float* hp = h2 + (size_t)m * HID;
    #pragma unroll 8
    for (int k = 0; k < HID; k++) acc = fmaf(hp[k], w3[k * 4 + j], acc);
    out[idx] = tanhf(acc) * 16.f + 16.f;
}

// -------------------- launch --------------------------------------------------
extern "C" void kernel_launch(void* const* d_in, const int* in_sizes, int n_in,
                              void* d_out, int out_size)
{
    const float* x   = (const float*)d_in[0];
    const float* ew1 = (const float*)d_in[1];
    const float* eb1 = (const float*)d_in[2];
    const float* ew2 = (const float*)d_in[3];
    const float* eb2 = (const float*)d_in[4];
    const float* ew3 = (const float*)d_in[5];
    const float* eb3 = (const float*)d_in[6];
    const float* dw2 = (const float*)d_in[7];
    const float* db2 = (const float*)d_in[8];
    const float* dw1 = (const float*)d_in[9];
    const float* db1 = (const float*)d_in[10];
    const float* ow  = (const float*)d_in[11];
    const float* ob  = (const float*)d_in[12];
    const float* lw1 = (const float*)d_in[13];
    const float* lb1 = (const float*)d_in[14];
    const float* lw2 = (const float*)d_in[15];
    const float* lb2 = (const float*)d_in[16];
    const float* lw3 = (const float*)d_in[17];
    const float* lb3 = (const float*)d_in[18];
    float* out = (float*)d_out;

    float *xt, *e1, *e2, *e3, *d2v, *feat, *h2, *part;
    cudaGetSymbolAddress((void**)&xt,   g_xt);
    cudaGetSymbolAddress((void**)&e1,   g_e1);
    cudaGetSymbolAddress((void**)&e2,   g_e2);
    cudaGetSymbolAddress((void**)&e3,   g_e3);
    cudaGetSymbolAddress((void**)&d2v,  g_d2);
    cudaGetSymbolAddress((void**)&feat, g_feat);
    cudaGetSymbolAddress((void**)&h2,   g_h2);
    cudaGetSymbolAddress((void**)&part, g_part);

    // smem bytes (R3-proven padded layouts; conv_up +18 floats for ow/ob)
    constexpr int SM_E1 = (3 * 8 * 9  + 8  + 2 * 3 * 32 * 33) * 4;                         // 26240
    constexpr int SM_E2 = (8 * 16 * 9 + 16 + 4 * 8 * 16 * 17) * 4;                         // 39488
    constexpr int SM_E3 = (16 * 32 * 9 + 32 + 8 * 16 * 8 * 9) * 4;                         // 55424
    constexpr int SM_D2 = (48 * 16 * 9 + 16 + 18 + 2 * (32 * 8 * 9 + 16 * 16 * 17)) * 4;   // 81032
    constexpr int SM_D1 = (24 * 8 * 9 + 8 + 18 + 2 * (16 * 16 * 17 + 8 * 32 * 33)) * 4;    // 109416

    cudaFuncSetAttribute((const void*)conv_std_k<8, 16, 8, 16, 4, 8, true>,
                         cudaFuncAttributeMaxDynamicSharedMemorySize, SM_E2);
    cudaFuncSetAttribute((const void*)conv_std_k<16, 32, 8, 8, 8, 8, true>,
                         cudaFuncAttributeMaxDynamicSharedMemorySize, SM_E3);
    cudaFuncSetAttribute((const void*)conv_up_k<32, 16, 16, 4, 16, 2, 8, false>,
                         cudaFuncAttributeMaxDynamicSharedMemorySize, SM_D2);
    cudaFuncSetAttribute((const void*)conv_up_k<16, 8, 8, 8, 32, 2, 8, true>,
                         cudaFuncAttributeMaxDynamicSharedMemorySize, SM_D1);

    // 1) permute
    permute_kernel<<<32 * 3 * 32, 256>>>(x, xt);
    // 2) e1 = relu(conv 3->8 @32)
    conv_std_k<3, 8, 8, 32, 2, 8, false><<<BT / 2, 256, SM_E1>>>(xt, ew1, eb1, e1);
    // 3) e2 = relu(conv pool(e1) 8->16 @16)
    conv_std_k<8, 16, 8, 16, 4, 8, true><<<BT / 4, 256, SM_E2>>>(e1, ew2, eb2, e2);
    // 4) e3 = relu(conv pool(e2) 16->32 @8)
    conv_std_k<16, 32, 8, 8, 8, 8, true><<<BT / 8, 256, SM_E3>>>(e2, ew3, eb3, e3);
    // 5) d2 = relu(conv [up(e3), e2] 48->16 @16)
    conv_up_k<32, 16, 16, 4, 16, 2, 8, false><<<BT / 2, 256, SM_D2>>>(
        e3, e2, dw2, db2, nullptr, nullptr, nullptr, d2v);
    // 6) d1 conv + 1x1 + softmax + masked features, fused -> feat
    conv_up_k<16, 8, 8, 8, 32, 2, 8, true><<<BT / 2, 256, SM_D1>>>(
        d2v, e1, dw1, db1, xt, ow, ob, feat);
    // 7) h1-partials = feat @ lw1 via split-K x8
    sgemm1_k<<<dim3(4, BT / 256, SPLITS), 256>>>(feat, lw1, part);
    // 8) h2 = relu(relu(lb1 + sum parts) @ lw2 + lb2)  (reduce fused in A-load)
    sgemm2_k<<<dim3(4, BT / 64), 256>>>(part, lb1, lw2, lb2, h2);
    // 9) out = tanh(h2 @ lw3 + lb3)*16+16
    loc3_kernel<<<(BT * 4 + 255) / 256, 256>>>(h2, lw3, lb3, out);
}